// round 16
// baseline (speedup 1.0000x reference)
#include <cuda_runtime.h>
#include <math.h>

// RoI max pooling (Caffe-style), bit-matching the JAX/XLA reference.
//   x    : [B=2, C=128, H=64, W=64] fp32
//   rois : [N=256, 5]  (batch_idx, x1, y1, x2, y2) image coords
//   out  : [N, C, 7, 7] fp32
//
// R16: R15 (chunk-4 explicit MLP) still latency-exposed (L1 29%, nothing
// saturated). Double in-flight depth: chunks of EIGHT back-to-back
// LDG.128 before any consumer. Past-end positions clamp to the last valid
// (h,w) -- duplicates are free under max and hit hot L1 lines. Typical
// 9-position window: 2 chunks -> ~1 exposed stall.
//
// CRITICAL (bit-exactness): XLA rewrites `roi / 7` into `roi * fl32(1/7)`.
// Must use the same reciprocal multiply or floor/ceil bin boundaries shift
// by 1 ulp on 7-divisible roi extents (caused rel_err 9.6e-2 in R1/R3).

#define B_  2
#define C_  128
#define H_  64
#define W_  64
#define S_  (H_ * W_)        // 4096
#define N_  256
#define OUTH_ 7
#define OUTW_ 7
#define NB_  (OUTH_ * OUTW_) // 49
#define SCALE_ (1.0f / 16.0f)
#define RCP7_  (1.0f / 7.0f) // fp32 RN: 0x3E124925
#define TSTRIDE_ 132         // smem tile row stride (floats), 16B-aligned

// channels-last scratch copy of x (static device global -> no allocation), 4 MB
__device__ float g_xt[B_ * S_ * C_];   // [b][h][w][c]

// ---------------------------------------------------------------- transpose
__global__ void transpose_kernel(const float* __restrict__ x) {
    __shared__ float t[32][33];
    const int b  = blockIdx.z;
    const int s0 = blockIdx.x * 32;
    const int c0 = blockIdx.y * 32;
    #pragma unroll
    for (int i = 0; i < 4; ++i) {
        const int c = c0 + threadIdx.y + i * 8;
        t[threadIdx.y + i * 8][threadIdx.x] =
            x[((size_t)b * C_ + c) * S_ + s0 + threadIdx.x];
    }
    __syncthreads();
    #pragma unroll
    for (int i = 0; i < 4; ++i) {
        const int s = s0 + threadIdx.y + i * 8;
        g_xt[((size_t)b * S_ + s) * C_ + c0 + threadIdx.x] =
            t[threadIdx.x][threadIdx.y + i * 8];
    }
}

// --------------------------------------------------------------------- pool
// Block = (ph, n), 256 threads = 8 warps. Warp w < 7 owns bin pw = w.
// Lane = channels [4*lane, 4*lane+4) via float4.
__global__ void roi_pool_kernel(const float* __restrict__ rois,
                                float* __restrict__ out) {
    __shared__ float tile[OUTW_ * TSTRIDE_];   // [pw][c]

    const int ph   = blockIdx.x;
    const int n    = blockIdx.y;
    const int t    = threadIdx.x;
    const int wid  = t >> 5;
    const int lane = t & 31;

    if (wid < OUTW_) {
        const int pw = wid;
        // uniform per-warp bounds (all lanes compute identically)
        const float* r = rois + n * 5;
        const int bidx = (int)r[0];
        const int xs = (int)rintf(r[1] * SCALE_);
        const int ys = (int)rintf(r[2] * SCALE_);
        const int xe = (int)rintf(r[3] * SCALE_);
        const int ye = (int)rintf(r[4] * SCALE_);
        const float roi_w = (float)max(xe - xs + 1, 1);
        const float roi_h = (float)max(ye - ys + 1, 1);
        // match XLA's divide -> multiply-by-reciprocal rewrite exactly
        const float bin_h = __fmul_rn(roi_h, RCP7_);
        const float bin_w = __fmul_rn(roi_w, RCP7_);
        int hs = (int)floorf(__fmul_rn((float)ph, bin_h)) + ys;
        int he = (int)ceilf(__fmul_rn((float)ph + 1.0f, bin_h)) + ys;
        int ws = (int)floorf(__fmul_rn((float)pw, bin_w)) + xs;
        int we = (int)ceilf(__fmul_rn((float)pw + 1.0f, bin_w)) + xs;
        hs = min(max(hs, 0), H_);
        he = min(max(he, 0), H_);
        ws = min(max(ws, 0), W_);
        we = min(max(we, 0), W_);

        const bool empty = (he <= hs) || (we <= ws);
        const int total = empty ? 0 : (he - hs) * (we - ws);

        float4 acc = make_float4(-INFINITY, -INFINITY, -INFINITY, -INFINITY);
        // base pointer in float4 units: offset(h,w) = h*2048 + w*32 (+lane)
        const float4* pB =
            (const float4*)(g_xt + bidx * (S_ * C_)) + lane;

        int h = hs, w = ws;
        for (int base = 0; base < total; base += 8) {
            // 8 addresses via incremental advance; past-end positions clamp
            // to the last valid (h,w) -> harmless duplicates under max
            int o[8];
            #pragma unroll
            for (int j = 0; j < 8; ++j) {
                o[j] = (h << 11) + (w << 5);
                ++w; if (w == we) { w = ws; h = (h + 1 < he) ? h + 1 : h; }
            }

            // 8 independent loads in flight before any consumer
            const float4 v0 = __ldg(pB + o[0]);
            const float4 v1 = __ldg(pB + o[1]);
            const float4 v2 = __ldg(pB + o[2]);
            const float4 v3 = __ldg(pB + o[3]);
            const float4 v4 = __ldg(pB + o[4]);
            const float4 v5 = __ldg(pB + o[5]);
            const float4 v6 = __ldg(pB + o[6]);
            const float4 v7 = __ldg(pB + o[7]);

            // FMNMX tree (depth 3) + acc merge
            acc.x = fmaxf(acc.x, fmaxf(fmaxf(fmaxf(v0.x, v1.x), fmaxf(v2.x, v3.x)),
                                       fmaxf(fmaxf(v4.x, v5.x), fmaxf(v6.x, v7.x))));
            acc.y = fmaxf(acc.y, fmaxf(fmaxf(fmaxf(v0.y, v1.y), fmaxf(v2.y, v3.y)),
                                       fmaxf(fmaxf(v4.y, v5.y), fmaxf(v6.y, v7.y))));
            acc.z = fmaxf(acc.z, fmaxf(fmaxf(fmaxf(v0.z, v1.z), fmaxf(v2.z, v3.z)),
                                       fmaxf(fmaxf(v4.z, v5.z), fmaxf(v6.z, v7.z))));
            acc.w = fmaxf(acc.w, fmaxf(fmaxf(fmaxf(v0.w, v1.w), fmaxf(v2.w, v3.w)),
                                       fmaxf(fmaxf(v4.w, v5.w), fmaxf(v6.w, v7.w))));
        }

        if (empty) acc = make_float4(0.0f, 0.0f, 0.0f, 0.0f);
        ((float4*)(tile + pw * TSTRIDE_))[lane] = acc;
    }
    __syncthreads();

    // writeback: out[n][c][ph*7 + pw]
    float* outn = out + (size_t)n * (C_ * NB_) + ph * OUTW_;
    for (int o = t; o < C_ * OUTW_; o += 256) {
        const int c  = o / OUTW_;
        const int pw = o - c * OUTW_;
        outn[c * NB_ + pw] = tile[pw * TSTRIDE_ + c];
    }
}

extern "C" void kernel_launch(void* const* d_in, const int* in_sizes, int n_in,
                              void* d_out, int out_size) {
    const float* x    = (const float*)d_in[0];
    const float* rois = (const float*)d_in[1];
    float* out = (float*)d_out;

    transpose_kernel<<<dim3(S_ / 32, C_ / 32, B_), dim3(32, 8)>>>(x);
    roi_pool_kernel<<<dim3(OUTH_, N_), 256>>>(rois, out);
}